// round 11
// baseline (speedup 1.0000x reference)
#include <cuda_runtime.h>
#include <cuda_bf16.h>
#include <cstdint>

#define NB 2
#define SLQ 2048
#define SLK 2048
#define DM 1024
#define NH 16
#define HD 64

#define XELEMS (NB * SLQ * DM)   // 4194304
#define WELEMS (DM * DM)         // 1048576
#define QKV_ELEMS (NB * NH * SLQ * HD)  // 4194304, head-major

// Split-bf16 operand scratch
__device__ __nv_bfloat16 g_Xh[2 * XELEMS];   // [query, key]
__device__ __nv_bfloat16 g_Xl[2 * XELEMS];
__device__ __nv_bfloat16 g_Wh[3 * WELEMS];   // [Wq, Wk, Wv]
__device__ __nv_bfloat16 g_Wl[3 * WELEMS];
// Projected Q/K/V in head-major split-bf16: idx = ((n*NH + h)*SLQ + s)*HD + d
// Q is pre-scaled by rsqrt(len[n]) in the proj epilogue.
__device__ __nv_bfloat16 g_Qh[QKV_ELEMS], g_Ql[QKV_ELEMS];
__device__ __nv_bfloat16 g_Kh[QKV_ELEMS], g_Kl[QKV_ELEMS];
__device__ __nv_bfloat16 g_Vh[QKV_ELEMS], g_Vl[QKV_ELEMS];
__device__ int g_len[NB];

// ---------------------------------------------------------------------------
// Baseline-PTX helpers (harness builds compute_103: no sm_103a-only features)
// ---------------------------------------------------------------------------
__device__ __forceinline__ uint32_t smem_u32(const void* p) {
    uint32_t a;
    asm("{ .reg .u64 t; cvta.to.shared.u64 t, %1; cvt.u32.u64 %0, t; }"
        : "=r"(a) : "l"(p));
    return a;
}
__device__ __forceinline__ void cp16(uint32_t saddr, const void* g) {
    asm volatile("cp.async.cg.shared.global [%0], [%1], 16;"
                 :: "r"(saddr), "l"(g));
}
#define CP_COMMIT() asm volatile("cp.async.commit_group;" ::: "memory")
#define CP_WAIT(N)  asm volatile("cp.async.wait_group %0;" :: "n"(N) : "memory")

__device__ __forceinline__ void ldm_x4(uint32_t* r, uint32_t addr) {
    asm volatile("ldmatrix.sync.aligned.m8n8.x4.shared.b16 {%0,%1,%2,%3}, [%4];"
                 : "=r"(r[0]), "=r"(r[1]), "=r"(r[2]), "=r"(r[3]) : "r"(addr));
}
__device__ __forceinline__ void ldm_x4_t(uint32_t* r, uint32_t addr) {
    asm volatile("ldmatrix.sync.aligned.m8n8.x4.trans.shared.b16 {%0,%1,%2,%3}, [%4];"
                 : "=r"(r[0]), "=r"(r[1]), "=r"(r[2]), "=r"(r[3]) : "r"(addr));
}
__device__ __forceinline__ void mma_bf16(float* c, const uint32_t* a,
                                         uint32_t b0, uint32_t b1) {
    asm volatile(
        "mma.sync.aligned.m16n8k16.row.col.f32.bf16.bf16.f32 "
        "{%0,%1,%2,%3}, {%4,%5,%6,%7}, {%8,%9}, {%0,%1,%2,%3};"
        : "+f"(c[0]), "+f"(c[1]), "+f"(c[2]), "+f"(c[3])
        : "r"(a[0]), "r"(a[1]), "r"(a[2]), "r"(a[3]), "r"(b0), "r"(b1));
}
__device__ __forceinline__ uint32_t pack_bf16(float lo, float hi) {
    __nv_bfloat162 t = __floats2bfloat162_rn(lo, hi);  // .x = lo half
    return *reinterpret_cast<uint32_t*>(&t);
}
// swizzled offset within a [rows][128B] tile
__device__ __forceinline__ uint32_t sw(int r, int ch) {
    return (uint32_t)(r * 128 + ((ch ^ (r & 7)) << 4));
}

// ---------------------------------------------------------------------------
// Fast e^x (avoids MUFU throughput wall)
// ---------------------------------------------------------------------------
__device__ __forceinline__ float fast_exp(float x) {
    float y = fmaxf(x * 1.4426950408889634f, -126.0f);
    float t = y + 12582912.0f;
    int   ki = __float_as_int(t) - 0x4B400000;
    float kf = t - 12582912.0f;
    float f  = y - kf;
    float p = 1.3333558146e-3f;
    p = fmaf(p, f, 9.6181291076e-3f);
    p = fmaf(p, f, 5.5504108664e-2f);
    p = fmaf(p, f, 2.4022650696e-1f);
    p = fmaf(p, f, 6.9314718056e-1f);
    p = fmaf(p, f, 1.0f);
    return __int_as_float(__float_as_int(p) + (ki << 23));
}

// ---------------------------------------------------------------------------
// Kernel 0: valid key lengths (dtype-agnostic mask scan). One block per batch.
// ---------------------------------------------------------------------------
__global__ void len_kernel(const unsigned int* __restrict__ pm) {
    __shared__ int flag;
    __shared__ int red[256];
    const int tid = threadIdx.x;
    const int n = blockIdx.x;
    if (tid == 0) flag = 0;
    __syncthreads();
    int ev = 0;
    for (int j = tid; j < 1024; j += 256)
        if (pm[j] == 0x01010101u) ev |= 1;   // packed-uint8 padding run
    if (ev) atomicOr(&flag, ev);
    __syncthreads();
    const bool is_u8 = (flag & 1);
    int c = 0;
    if (is_u8) {
        for (int j = tid; j < 512; j += 256) {
            unsigned w = pm[n * 512 + j];
            c += ((w & 0x000000FFu) == 0) + ((w & 0x0000FF00u) == 0)
               + ((w & 0x00FF0000u) == 0) + ((w & 0xFF000000u) == 0);
        }
    } else {
        for (int j = tid; j < SLK; j += 256)
            c += (pm[n * SLK + j] == 0u);
    }
    red[tid] = c;
    __syncthreads();
    for (int s = 128; s > 0; s >>= 1) {
        if (tid < s) red[tid] += red[tid + s];
        __syncthreads();
    }
    if (tid == 0) g_len[n] = red[0];
}

// ---------------------------------------------------------------------------
// Kernel 1: fp32 -> split bf16 (hi + lo)
// ---------------------------------------------------------------------------
__global__ __launch_bounds__(256)
void split_kernel(const float* __restrict__ query, const float* __restrict__ key,
                  const float* __restrict__ Wq, const float* __restrict__ Wk,
                  const float* __restrict__ Wv) {
    const int z = blockIdx.y;
    const float* src;
    __nv_bfloat16 *dh, *dl;
    int n4;
    if (z == 0)      { src = query; dh = g_Xh;          dl = g_Xl;          n4 = XELEMS / 4; }
    else if (z == 1) { src = key;   dh = g_Xh + XELEMS; dl = g_Xl + XELEMS; n4 = XELEMS / 4; }
    else {
        src = (z == 2) ? Wq : ((z == 3) ? Wk : Wv);
        dh = g_Wh + (z - 2) * WELEMS; dl = g_Wl + (z - 2) * WELEMS; n4 = WELEMS / 4;
    }
    int i = blockIdx.x * 256 + threadIdx.x;
    if (i >= n4) return;
    float4 v = ((const float4*)src)[i];
    __nv_bfloat16 h0 = __float2bfloat16_rn(v.x);
    __nv_bfloat16 h1 = __float2bfloat16_rn(v.y);
    __nv_bfloat16 h2 = __float2bfloat16_rn(v.z);
    __nv_bfloat16 h3 = __float2bfloat16_rn(v.w);
    __nv_bfloat16 l0 = __float2bfloat16_rn(v.x - __bfloat162float(h0));
    __nv_bfloat16 l1 = __float2bfloat16_rn(v.y - __bfloat162float(h1));
    __nv_bfloat16 l2 = __float2bfloat16_rn(v.z - __bfloat162float(h2));
    __nv_bfloat16 l3 = __float2bfloat16_rn(v.w - __bfloat162float(h3));
    ((__nv_bfloat162*)dh)[2 * i]     = __nv_bfloat162(h0, h1);
    ((__nv_bfloat162*)dh)[2 * i + 1] = __nv_bfloat162(h2, h3);
    ((__nv_bfloat162*)dl)[2 * i]     = __nv_bfloat162(l0, l1);
    ((__nv_bfloat162*)dl)[2 * i + 1] = __nv_bfloat162(l2, l3);
}

// ---------------------------------------------------------------------------
// Kernel 2: projection GEMM via mma.sync bf16, split x3.
// Epilogue: Q (z==0) is pre-scaled by rsqrt(len[batch]) before splitting.
// ---------------------------------------------------------------------------
#define PSTAGE 65536   // Ah(16K) Al(16K) Bh(16K) Bl(16K)

__global__ __launch_bounds__(256, 1)
void proj_mma(void) {
    extern __shared__ char psm[];
    const uint32_t sbase = smem_u32(psm);
    const int tid  = threadIdx.x;
    const int wid  = tid >> 5;
    const int lane = tid & 31;
    const int wm = wid & 3;
    const int wn = wid >> 2;
    const int z  = blockIdx.z;
    const int n0 = blockIdx.x * 128;
    const int m0 = blockIdx.y * 128;

    const __nv_bfloat16* Ah = g_Xh + ((z == 0) ? 0 : XELEMS);
    const __nv_bfloat16* Al = g_Xl + ((z == 0) ? 0 : XELEMS);
    const __nv_bfloat16* Bh = g_Wh + z * WELEMS;
    const __nv_bfloat16* Bl = g_Wl + z * WELEMS;
    __nv_bfloat16* Ch = (z == 0) ? g_Qh : ((z == 1) ? g_Kh : g_Vh);
    __nv_bfloat16* Cl = (z == 0) ? g_Ql : ((z == 1) ? g_Kl : g_Vl);

    const int lr0 = tid >> 3;
    const int lch = tid & 7;

    auto load_stage = [&](int s, int kb) {
        const uint32_t st = sbase + (uint32_t)(s & 1) * PSTAGE;
#pragma unroll
        for (int p = 0; p < 4; ++p) {
            int r = lr0 + p * 32;
            uint32_t o = sw(r, lch);
            cp16(st + o,          Ah + (size_t)(m0 + r) * DM + kb + lch * 8);
            cp16(st + 16384 + o,  Al + (size_t)(m0 + r) * DM + kb + lch * 8);
            cp16(st + 32768 + o,  Bh + (size_t)(n0 + r) * DM + kb + lch * 8);
            cp16(st + 49152 + o,  Bl + (size_t)(n0 + r) * DM + kb + lch * 8);
        }
        CP_COMMIT();
    };

    float c[2][8][4];
#pragma unroll
    for (int mt = 0; mt < 2; ++mt)
#pragma unroll
        for (int nt = 0; nt < 8; ++nt)
#pragma unroll
            for (int q = 0; q < 4; ++q) c[mt][nt][q] = 0.0f;

    load_stage(0, 0);

    for (int s = 0; s < 16; ++s) {
        if (s < 15) load_stage(s + 1, (s + 1) * 64);
        if (s < 15) { CP_WAIT(1); } else { CP_WAIT(0); }
        __syncthreads();

        const uint32_t st = sbase + (uint32_t)(s & 1) * PSTAGE;
        const int ar = wm * 32 + (lane & 15);
        const int ach_sel = lane >> 4;
        const int br = wn * 64 + (lane & 7) + ((lane >> 4) << 3);
        const int bch_sel = (lane >> 3) & 1;

#pragma unroll
        for (int kc = 0; kc < 4; ++kc) {
            uint32_t ah[2][4], al[2][4];
#pragma unroll
            for (int mt = 0; mt < 2; ++mt) {
                uint32_t ao = sw(ar + mt * 16, 2 * kc + ach_sel);
                ldm_x4(ah[mt], st + ao);
                ldm_x4(al[mt], st + 16384 + ao);
            }
            uint32_t bh[4][4], bl[4][4];
#pragma unroll
            for (int nt2 = 0; nt2 < 4; ++nt2) {
                uint32_t bo = sw(br + nt2 * 16, 2 * kc + bch_sel);
                ldm_x4(bh[nt2], st + 32768 + bo);
                ldm_x4(bl[nt2], st + 49152 + bo);
            }
#pragma unroll
            for (int mt = 0; mt < 2; ++mt)
#pragma unroll
                for (int nt2 = 0; nt2 < 4; ++nt2) {
#pragma unroll
                    for (int t = 0; t < 2; ++t) {
                        float* cc = c[mt][2 * nt2 + t];
                        uint32_t b0 = bh[nt2][2 * t], b1 = bh[nt2][2 * t + 1];
                        uint32_t l0 = bl[nt2][2 * t], l1 = bl[nt2][2 * t + 1];
                        mma_bf16(cc, ah[mt], b0, b1);
                        mma_bf16(cc, ah[mt], l0, l1);
                        mma_bf16(cc, al[mt], b0, b1);
                    }
                }
        }
        __syncthreads();
    }

    // per-batch Q pre-scale (1/sqrt(valid_len)); 1.0 for K/V
    float rs0 = 1.0f, rs1 = 1.0f;
    if (z == 0) {
        rs0 = rsqrtf((float)g_len[0]);
        rs1 = rsqrtf((float)g_len[1]);
    }

#pragma unroll
    for (int mt = 0; mt < 2; ++mt) {
#pragma unroll
        for (int nt = 0; nt < 8; ++nt) {
            int gn = n0 + wn * 64 + nt * 8 + 2 * (lane & 3);
            int h = gn >> 6, d = gn & 63;
#pragma unroll
            for (int half = 0; half < 2; ++half) {
                int gm = m0 + wm * 32 + mt * 16 + (lane >> 2) + half * 8;
                int nb = gm >> 11, ss = gm & 2047;
                float scale = nb ? rs1 : rs0;
                size_t idx = (((size_t)nb * NH + h) * SLQ + ss) * HD + d;
                float v0 = c[mt][nt][2 * half] * scale;
                float v1 = c[mt][nt][2 * half + 1] * scale;
                float h0 = __bfloat162float(__float2bfloat16_rn(v0));
                float h1 = __bfloat162float(__float2bfloat16_rn(v1));
                *(uint32_t*)(Ch + idx) = pack_bf16(h0, h1);
                *(uint32_t*)(Cl + idx) = pack_bf16(v0 - h0, v1 - h1);
            }
        }
    }
}

// ---------------------------------------------------------------------------
// Kernel 3: flash attention via mma.sync bf16.
// QK^T uses 2-term split (Qh+Ql)·Kh (Kl dropped: score err ~1e-4 abs, safe).
// P·V keeps full 3-term split. Interior tiles skip masking entirely (Q is
// pre-scaled). KV stage = Kh|Vh|Vl = 24KB, double-buffered (48KB); 4 CTAs/SM.
// ---------------------------------------------------------------------------
__global__ __launch_bounds__(128, 4)
void attn_mma(float* __restrict__ out) {
    extern __shared__ char dsm[];
    const uint32_t sb = smem_u32(dsm);
    const int tid  = threadIdx.x;
    const int wid  = tid >> 5;
    const int lane = tid & 31;
    // heavy (high-qb) blocks first to fill the tail wave with short blocks
    const int qb = (SLQ / 64 - 1) - blockIdx.x;
    const int h = blockIdx.y, nb = blockIdx.z;
    const int q0 = qb * 64;

    const int len = g_len[nb];

    const size_t headQ = (((size_t)nb * NH + h) * SLQ) * HD;
    const size_t headK = (((size_t)nb * NH + h) * SLK) * HD;

    const int lr = tid >> 3;          // 0..15 (+16 per p)
    const int lch = tid & 7;

    // --- preamble: Q into smem[0,16K), frags to regs, then area is recycled
    {
#pragma unroll
        for (int p = 0; p < 4; ++p) {
            int rr = lr + p * 16;
            uint32_t o = sw(rr, lch);
            const size_t g = headQ + (size_t)(q0 + rr) * HD + lch * 8;
            cp16(sb + o,        g_Qh + g);
            cp16(sb + 8192 + o, g_Ql + g);
        }
        CP_COMMIT();
    }
    CP_WAIT(0);
    __syncthreads();

    uint32_t qa_h[4][4], qa_l[4][4];
    {
        const int ar = wid * 16 + (lane & 15);
        const int asel = lane >> 4;
#pragma unroll
        for (int kc = 0; kc < 4; ++kc) {
            uint32_t o = sw(ar, 2 * kc + asel);
            ldm_x4(qa_h[kc], sb + o);
            ldm_x4(qa_l[kc], sb + 8192 + o);
        }
    }
    __syncthreads();   // all warps done reading Q area before KV overwrites it

    const int nkt_c = qb + 1;
    const int nkt_l = (len + 63) >> 6;
    const int nkt = (nkt_c < nkt_l) ? nkt_c : nkt_l;

    // KV stage loader: buf b in {0,1}, layout Kh|Vh|Vl @ 8KB each (24KB)
    auto kvload = [&](int b, int k0) {
        const uint32_t base = sb + (uint32_t)b * 24576;
#pragma unroll
        for (int p = 0; p < 4; ++p) {
            int rr = lr + p * 16;
            uint32_t o = sw(rr, lch);
            const size_t g = headK + (size_t)(k0 + rr) * HD + lch * 8;
            cp16(base + o,         g_Kh + g);
            cp16(base + 8192 + o,  g_Vh + g);
            cp16(base + 16384 + o, g_Vl + g);
        }
        CP_COMMIT();
    };
    kvload(0, 0);

    float o_[8][4];
#pragma unroll
    for (int nt = 0; nt < 8; ++nt)
#pragma unroll
        for (int q = 0; q < 4; ++q) o_[nt][q] = 0.0f;
    float m0r = -1e30f, m1r = -1e30f, l0r = 0.0f, l1r = 0.0f;

    const int row0 = q0 + wid * 16 + (lane >> 2);   // c0,c1 row
    const int kbr = (lane & 7) + ((lane >> 4) << 3);
    const int kbsel = (lane >> 3) & 1;
    const int vbr = (lane & 7) + (((lane >> 3) & 1) << 3);
    const int vbsel = lane >> 4;

    for (int kt = 0; kt < nkt; ++kt) {
        const int k0 = kt * 64;
        CP_WAIT(0);        // KV[kt] landed
        __syncthreads();   // visible to all; prior tile reads complete
        if (kt + 1 < nkt) kvload((kt + 1) & 1, k0 + 64);  // prefetch

        const uint32_t base = sb + (uint32_t)(kt & 1) * 24576;

        // S = Q K^T  (2-term split: Qh·Kh + Ql·Kh)
        float s[8][4];
#pragma unroll
        for (int nt = 0; nt < 8; ++nt)
#pragma unroll
            for (int q = 0; q < 4; ++q) s[nt][q] = 0.0f;

#pragma unroll
        for (int nt2 = 0; nt2 < 4; ++nt2) {
#pragma unroll
            for (int kc = 0; kc < 4; ++kc) {
                uint32_t bo = sw(nt2 * 16 + kbr, 2 * kc + kbsel);
                uint32_t kh[4];
                ldm_x4(kh, base + bo);
#pragma unroll
                for (int t = 0; t < 2; ++t) {
                    float* cc = s[2 * nt2 + t];
                    mma_bf16(cc, qa_h[kc], kh[2 * t], kh[2 * t + 1]);
                    mma_bf16(cc, qa_l[kc], kh[2 * t], kh[2 * t + 1]);
                }
            }
        }

        // masking only on boundary tiles (diagonal or length-edge);
        // Q is pre-scaled so interior tiles need no elementwise pass.
        if (kt == qb || k0 + 64 > len) {
#pragma unroll
            for (int nt = 0; nt < 8; ++nt) {
                int kcol = k0 + nt * 8 + 2 * (lane & 3);
#pragma unroll
                for (int q = 0; q < 4; ++q) {
                    int kk = kcol + (q & 1);
                    int qq = row0 + (q >> 1) * 8;
                    if (kk > qq || kk >= len) s[nt][q] = -30000.0f;
                }
            }
        }

        // online softmax (rows r0 = c0,c1 ; r1 = r0+8 = c2,c3)
        float mx0 = -1e30f, mx1 = -1e30f;
#pragma unroll
        for (int nt = 0; nt < 8; ++nt) {
            mx0 = fmaxf(mx0, fmaxf(s[nt][0], s[nt][1]));
            mx1 = fmaxf(mx1, fmaxf(s[nt][2], s[nt][3]));
        }
        mx0 = fmaxf(mx0, __shfl_xor_sync(0xffffffffu, mx0, 1));
        mx0 = fmaxf(mx0, __shfl_xor_sync(0xffffffffu, mx0, 2));
        mx1 = fmaxf(mx1, __shfl_xor_sync(0xffffffffu, mx1, 1));
        mx1 = fmaxf(mx1, __shfl_xor_sync(0xffffffffu, mx1, 2));
        float mn0 = fmaxf(m0r, mx0), mn1 = fmaxf(m1r, mx1);
        float a0 = fast_exp(m0r - mn0), a1 = fast_exp(m1r - mn1);
        float sum0 = 0.0f, sum1 = 0.0f;
#pragma unroll
        for (int nt = 0; nt < 8; ++nt) {
            s[nt][0] = fast_exp(s[nt][0] - mn0);
            s[nt][1] = fast_exp(s[nt][1] - mn0);
            s[nt][2] = fast_exp(s[nt][2] - mn1);
            s[nt][3] = fast_exp(s[nt][3] - mn1);
            sum0 += s[nt][0] + s[nt][1];
            sum1 += s[nt][2] + s[nt][3];
        }
        sum0 += __shfl_xor_sync(0xffffffffu, sum0, 1);
        sum0 += __shfl_xor_sync(0xffffffffu, sum0, 2);
        sum1 += __shfl_xor_sync(0xffffffffu, sum1, 1);
        sum1 += __shfl_xor_sync(0xffffffffu, sum1, 2);
        l0r = l0r * a0 + sum0;  m0r = mn0;
        l1r = l1r * a1 + sum1;  m1r = mn1;

#pragma unroll
        for (int nt = 0; nt < 8; ++nt) {
            o_[nt][0] *= a0; o_[nt][1] *= a0;
            o_[nt][2] *= a1; o_[nt][3] *= a1;
        }

        // P·V (full 3-term split)
#pragma unroll
        for (int kc = 0; kc < 4; ++kc) {
            uint32_t pa_h[4], pa_l[4];
#pragma unroll
            for (int t2 = 0; t2 < 2; ++t2) {
                const float* sv = s[2 * kc + t2];
                float h0 = __bfloat162float(__float2bfloat16_rn(sv[0]));
                float h1 = __bfloat162float(__float2bfloat16_rn(sv[1]));
                float h2 = __bfloat162float(__float2bfloat16_rn(sv[2]));
                float h3 = __bfloat162float(__float2bfloat16_rn(sv[3]));
                pa_h[2 * t2]     = pack_bf16(h0, h1);
                pa_h[2 * t2 + 1] = pack_bf16(h2, h3);
                pa_l[2 * t2]     = pack_bf16(sv[0] - h0, sv[1] - h1);
                pa_l[2 * t2 + 1] = pack_bf16(sv[2] - h2, sv[3] - h3);
            }
#pragma unroll
            for (int dn2 = 0; dn2 < 4; ++dn2) {
                uint32_t vo = sw(kc * 16 + vbr, 2 * dn2 + vbsel);
                uint32_t vh[4], vl[4];
                ldm_x4_t(vh, base + 8192 + vo);
                ldm_x4_t(vl, base + 16384 + vo);
#pragma unroll
                for (int t = 0; t < 2; ++t) {
                    float* cc = o_[2 * dn2 + t];
                    mma_bf16(cc, pa_h, vh[2 * t], vh[2 * t + 1]);
                    mma_bf16(cc, pa_h, vl[2 * t], vl[2 * t + 1]);
                    mma_bf16(cc, pa_l, vh[2 * t], vh[2 * t + 1]);
                }
            }
        }
    }

    // write O
    float inv0 = 1.0f / l0r, inv1 = 1.0f / l1r;
#pragma unroll
    for (int nt = 0; nt < 8; ++nt) {
        int d = h * HD + nt * 8 + 2 * (lane & 3);
        float2 r0 = make_float2(o_[nt][0] * inv0, o_[nt][1] * inv0);
        float2 r1 = make_float2(o_[nt][2] * inv1, o_[nt][3] * inv1);
        *(float2*)(out + ((size_t)nb * SLQ + row0) * DM + d) = r0;
        *(float2*)(out + ((size_t)nb * SLQ + row0 + 8) * DM + d) = r1;
    }
}

// ---------------------------------------------------------------------------
extern "C" void kernel_launch(void* const* d_in, const int* in_sizes, int n_in,
                              void* d_out, int out_size) {
    const float* query = (const float*)d_in[0];
    const float* key   = (const float*)d_in[1];
    const float* Wq    = (const float*)d_in[2];
    const float* Wk    = (const float*)d_in[3];
    const float* Wv    = (const float*)d_in[4];
    const unsigned int* pm = (const unsigned int*)d_in[6];
    float* out = (float*)d_out;

    cudaFuncSetAttribute(proj_mma, cudaFuncAttributeMaxDynamicSharedMemorySize,
                         2 * PSTAGE);
    cudaFuncSetAttribute(attn_mma, cudaFuncAttributeMaxDynamicSharedMemorySize,
                         49152);

    len_kernel<<<NB, 256>>>(pm);
    split_kernel<<<dim3(XELEMS / 4 / 256, 5), 256>>>(query, key, Wq, Wk, Wv);
    proj_mma<<<dim3(DM / 128, (NB * SLQ) / 128, 3), 256, 2 * PSTAGE>>>();
    attn_mma<<<dim3(SLQ / 64, NH, NB), 128, 49152>>>(out);
}

// round 12
// speedup vs baseline: 1.4336x; 1.4336x over previous
#include <cuda_runtime.h>
#include <cuda_bf16.h>
#include <cstdint>

#define NB 2
#define SLQ 2048
#define SLK 2048
#define DM 1024
#define NH 16
#define HD 64

#define XELEMS (NB * SLQ * DM)   // 4194304
#define WELEMS (DM * DM)         // 1048576
#define QKV_ELEMS (NB * NH * SLQ * HD)  // 4194304, head-major

// Split-bf16 operand scratch
__device__ __nv_bfloat16 g_Xh[2 * XELEMS];   // [query, key]
__device__ __nv_bfloat16 g_Xl[2 * XELEMS];
__device__ __nv_bfloat16 g_Wh[3 * WELEMS];   // [Wq, Wk, Wv]
__device__ __nv_bfloat16 g_Wl[3 * WELEMS];
// Projected Q/K/V in head-major split-bf16: idx = ((n*NH + h)*SLQ + s)*HD + d
__device__ __nv_bfloat16 g_Qh[QKV_ELEMS], g_Ql[QKV_ELEMS];
__device__ __nv_bfloat16 g_Kh[QKV_ELEMS], g_Kl[QKV_ELEMS];
__device__ __nv_bfloat16 g_Vh[QKV_ELEMS], g_Vl[QKV_ELEMS];
__device__ int g_len[NB];

// ---------------------------------------------------------------------------
// Baseline-PTX helpers (harness builds compute_103: no sm_103a-only features)
// ---------------------------------------------------------------------------
__device__ __forceinline__ uint32_t smem_u32(const void* p) {
    uint32_t a;
    asm("{ .reg .u64 t; cvta.to.shared.u64 t, %1; cvt.u32.u64 %0, t; }"
        : "=r"(a) : "l"(p));
    return a;
}
__device__ __forceinline__ void cp16(uint32_t saddr, const void* g) {
    asm volatile("cp.async.cg.shared.global [%0], [%1], 16;"
                 :: "r"(saddr), "l"(g));
}
#define CP_COMMIT() asm volatile("cp.async.commit_group;" ::: "memory")
#define CP_WAIT(N)  asm volatile("cp.async.wait_group %0;" :: "n"(N) : "memory")

__device__ __forceinline__ void ldm_x4(uint32_t* r, uint32_t addr) {
    asm volatile("ldmatrix.sync.aligned.m8n8.x4.shared.b16 {%0,%1,%2,%3}, [%4];"
                 : "=r"(r[0]), "=r"(r[1]), "=r"(r[2]), "=r"(r[3]) : "r"(addr));
}
__device__ __forceinline__ void ldm_x4_t(uint32_t* r, uint32_t addr) {
    asm volatile("ldmatrix.sync.aligned.m8n8.x4.trans.shared.b16 {%0,%1,%2,%3}, [%4];"
                 : "=r"(r[0]), "=r"(r[1]), "=r"(r[2]), "=r"(r[3]) : "r"(addr));
}
__device__ __forceinline__ void mma_bf16(float* c, const uint32_t* a,
                                         uint32_t b0, uint32_t b1) {
    asm volatile(
        "mma.sync.aligned.m16n8k16.row.col.f32.bf16.bf16.f32 "
        "{%0,%1,%2,%3}, {%4,%5,%6,%7}, {%8,%9}, {%0,%1,%2,%3};"
        : "+f"(c[0]), "+f"(c[1]), "+f"(c[2]), "+f"(c[3])
        : "r"(a[0]), "r"(a[1]), "r"(a[2]), "r"(a[3]), "r"(b0), "r"(b1));
}
__device__ __forceinline__ uint32_t pack_bf16(float lo, float hi) {
    __nv_bfloat162 t = __floats2bfloat162_rn(lo, hi);  // .x = lo half
    return *reinterpret_cast<uint32_t*>(&t);
}
// swizzled offset within a [rows][128B] tile
__device__ __forceinline__ uint32_t sw(int r, int ch) {
    return (uint32_t)(r * 128 + ((ch ^ (r & 7)) << 4));
}

// ---------------------------------------------------------------------------
// Fast e^(x*c) : c pre-multiplied scale folds softmax scaling into the exp's
// existing range-reduction multiply (avoids MUFU and the per-score FMUL pass).
// ---------------------------------------------------------------------------
__device__ __forceinline__ float fast_exp_sc(float x, float c) {
    float y = fmaxf(x * c, -126.0f);    // c = rscale * log2(e)
    float t = y + 12582912.0f;          // 1.5 * 2^23 magic
    int   ki = __float_as_int(t) - 0x4B400000;
    float kf = t - 12582912.0f;
    float f  = y - kf;
    float p = 1.3333558146e-3f;
    p = fmaf(p, f, 9.6181291076e-3f);
    p = fmaf(p, f, 5.5504108664e-2f);
    p = fmaf(p, f, 2.4022650696e-1f);
    p = fmaf(p, f, 6.9314718056e-1f);
    p = fmaf(p, f, 1.0f);
    return __int_as_float(__float_as_int(p) + (ki << 23));
}

// ---------------------------------------------------------------------------
// Kernel 0: valid key lengths (dtype-agnostic mask scan). One block per batch.
// ---------------------------------------------------------------------------
__global__ void len_kernel(const unsigned int* __restrict__ pm) {
    __shared__ int flag;
    __shared__ int red[256];
    const int tid = threadIdx.x;
    const int n = blockIdx.x;
    if (tid == 0) flag = 0;
    __syncthreads();
    int ev = 0;
    for (int j = tid; j < 1024; j += 256)
        if (pm[j] == 0x01010101u) ev |= 1;   // packed-uint8 padding run
    if (ev) atomicOr(&flag, ev);
    __syncthreads();
    const bool is_u8 = (flag & 1);
    int c = 0;
    if (is_u8) {
        for (int j = tid; j < 512; j += 256) {
            unsigned w = pm[n * 512 + j];
            c += ((w & 0x000000FFu) == 0) + ((w & 0x0000FF00u) == 0)
               + ((w & 0x00FF0000u) == 0) + ((w & 0xFF000000u) == 0);
        }
    } else {
        for (int j = tid; j < SLK; j += 256)
            c += (pm[n * SLK + j] == 0u);
    }
    red[tid] = c;
    __syncthreads();
    for (int s = 128; s > 0; s >>= 1) {
        if (tid < s) red[tid] += red[tid + s];
        __syncthreads();
    }
    if (tid == 0) g_len[n] = red[0];
}

// ---------------------------------------------------------------------------
// Kernel 1: fp32 -> split bf16 (hi + lo)
// ---------------------------------------------------------------------------
__global__ __launch_bounds__(256)
void split_kernel(const float* __restrict__ query, const float* __restrict__ key,
                  const float* __restrict__ Wq, const float* __restrict__ Wk,
                  const float* __restrict__ Wv) {
    const int z = blockIdx.y;
    const float* src;
    __nv_bfloat16 *dh, *dl;
    int n4;
    if (z == 0)      { src = query; dh = g_Xh;          dl = g_Xl;          n4 = XELEMS / 4; }
    else if (z == 1) { src = key;   dh = g_Xh + XELEMS; dl = g_Xl + XELEMS; n4 = XELEMS / 4; }
    else {
        src = (z == 2) ? Wq : ((z == 3) ? Wk : Wv);
        dh = g_Wh + (z - 2) * WELEMS; dl = g_Wl + (z - 2) * WELEMS; n4 = WELEMS / 4;
    }
    int i = blockIdx.x * 256 + threadIdx.x;
    if (i >= n4) return;
    float4 v = ((const float4*)src)[i];
    __nv_bfloat16 h0 = __float2bfloat16_rn(v.x);
    __nv_bfloat16 h1 = __float2bfloat16_rn(v.y);
    __nv_bfloat16 h2 = __float2bfloat16_rn(v.z);
    __nv_bfloat16 h3 = __float2bfloat16_rn(v.w);
    __nv_bfloat16 l0 = __float2bfloat16_rn(v.x - __bfloat162float(h0));
    __nv_bfloat16 l1 = __float2bfloat16_rn(v.y - __bfloat162float(h1));
    __nv_bfloat16 l2 = __float2bfloat16_rn(v.z - __bfloat162float(h2));
    __nv_bfloat16 l3 = __float2bfloat16_rn(v.w - __bfloat162float(h3));
    ((__nv_bfloat162*)dh)[2 * i]     = __nv_bfloat162(h0, h1);
    ((__nv_bfloat162*)dh)[2 * i + 1] = __nv_bfloat162(h2, h3);
    ((__nv_bfloat162*)dl)[2 * i]     = __nv_bfloat162(l0, l1);
    ((__nv_bfloat162*)dl)[2 * i + 1] = __nv_bfloat162(l2, l3);
}

// ---------------------------------------------------------------------------
// Kernel 2: projection GEMM via mma.sync bf16, split x3 (proven R4/R7 version).
// ---------------------------------------------------------------------------
#define PSTAGE 65536   // Ah(16K) Al(16K) Bh(16K) Bl(16K)

__global__ __launch_bounds__(256, 1)
void proj_mma(void) {
    extern __shared__ char psm[];
    const uint32_t sbase = smem_u32(psm);
    const int tid  = threadIdx.x;
    const int wid  = tid >> 5;
    const int lane = tid & 31;
    const int wm = wid & 3;
    const int wn = wid >> 2;
    const int z  = blockIdx.z;
    const int n0 = blockIdx.x * 128;
    const int m0 = blockIdx.y * 128;

    const __nv_bfloat16* Ah = g_Xh + ((z == 0) ? 0 : XELEMS);
    const __nv_bfloat16* Al = g_Xl + ((z == 0) ? 0 : XELEMS);
    const __nv_bfloat16* Bh = g_Wh + z * WELEMS;
    const __nv_bfloat16* Bl = g_Wl + z * WELEMS;
    __nv_bfloat16* Ch = (z == 0) ? g_Qh : ((z == 1) ? g_Kh : g_Vh);
    __nv_bfloat16* Cl = (z == 0) ? g_Ql : ((z == 1) ? g_Kl : g_Vl);

    const int lr0 = tid >> 3;
    const int lch = tid & 7;

    auto load_stage = [&](int s, int kb) {
        const uint32_t st = sbase + (uint32_t)(s & 1) * PSTAGE;
#pragma unroll
        for (int p = 0; p < 4; ++p) {
            int r = lr0 + p * 32;
            uint32_t o = sw(r, lch);
            cp16(st + o,          Ah + (size_t)(m0 + r) * DM + kb + lch * 8);
            cp16(st + 16384 + o,  Al + (size_t)(m0 + r) * DM + kb + lch * 8);
            cp16(st + 32768 + o,  Bh + (size_t)(n0 + r) * DM + kb + lch * 8);
            cp16(st + 49152 + o,  Bl + (size_t)(n0 + r) * DM + kb + lch * 8);
        }
        CP_COMMIT();
    };

    float c[2][8][4];
#pragma unroll
    for (int mt = 0; mt < 2; ++mt)
#pragma unroll
        for (int nt = 0; nt < 8; ++nt)
#pragma unroll
            for (int q = 0; q < 4; ++q) c[mt][nt][q] = 0.0f;

    load_stage(0, 0);

    for (int s = 0; s < 16; ++s) {
        if (s < 15) load_stage(s + 1, (s + 1) * 64);
        if (s < 15) { CP_WAIT(1); } else { CP_WAIT(0); }
        __syncthreads();

        const uint32_t st = sbase + (uint32_t)(s & 1) * PSTAGE;
        const int ar = wm * 32 + (lane & 15);
        const int ach_sel = lane >> 4;
        const int br = wn * 64 + (lane & 7) + ((lane >> 4) << 3);
        const int bch_sel = (lane >> 3) & 1;

#pragma unroll
        for (int kc = 0; kc < 4; ++kc) {
            uint32_t ah[2][4], al[2][4];
#pragma unroll
            for (int mt = 0; mt < 2; ++mt) {
                uint32_t ao = sw(ar + mt * 16, 2 * kc + ach_sel);
                ldm_x4(ah[mt], st + ao);
                ldm_x4(al[mt], st + 16384 + ao);
            }
            uint32_t bh[4][4], bl[4][4];
#pragma unroll
            for (int nt2 = 0; nt2 < 4; ++nt2) {
                uint32_t bo = sw(br + nt2 * 16, 2 * kc + bch_sel);
                ldm_x4(bh[nt2], st + 32768 + bo);
                ldm_x4(bl[nt2], st + 49152 + bo);
            }
#pragma unroll
            for (int mt = 0; mt < 2; ++mt)
#pragma unroll
                for (int nt2 = 0; nt2 < 4; ++nt2) {
#pragma unroll
                    for (int t = 0; t < 2; ++t) {
                        float* cc = c[mt][2 * nt2 + t];
                        uint32_t b0 = bh[nt2][2 * t], b1 = bh[nt2][2 * t + 1];
                        uint32_t l0 = bl[nt2][2 * t], l1 = bl[nt2][2 * t + 1];
                        mma_bf16(cc, ah[mt], b0, b1);
                        mma_bf16(cc, ah[mt], l0, l1);
                        mma_bf16(cc, al[mt], b0, b1);
                    }
                }
        }
        __syncthreads();
    }

#pragma unroll
    for (int mt = 0; mt < 2; ++mt) {
#pragma unroll
        for (int nt = 0; nt < 8; ++nt) {
            int gn = n0 + wn * 64 + nt * 8 + 2 * (lane & 3);
            int h = gn >> 6, d = gn & 63;
#pragma unroll
            for (int half = 0; half < 2; ++half) {
                int gm = m0 + wm * 32 + mt * 16 + (lane >> 2) + half * 8;
                int nb = gm >> 11, ss = gm & 2047;
                size_t idx = (((size_t)nb * NH + h) * SLQ + ss) * HD + d;
                float v0 = c[mt][nt][2 * half], v1 = c[mt][nt][2 * half + 1];
                float h0 = __bfloat162float(__float2bfloat16_rn(v0));
                float h1 = __bfloat162float(__float2bfloat16_rn(v1));
                *(uint32_t*)(Ch + idx) = pack_bf16(h0, h1);
                *(uint32_t*)(Cl + idx) = pack_bf16(v0 - h0, v1 - h1);
            }
        }
    }
}

// ---------------------------------------------------------------------------
// Kernel 3: flash attention via mma.sync bf16 split x3 (R7 structure).
// Change vs R7: score scaling folded into exp (softmax(s*r) computed with
// raw-score max and exp((s-m)*r)); masking pass runs only on the diagonal
// and length-boundary tiles. Numerically equivalent otherwise.
// ---------------------------------------------------------------------------
__global__ __launch_bounds__(128)
void attn_mma(float* __restrict__ out) {
    extern __shared__ char dsm[];
    const uint32_t sb = smem_u32(dsm);
    const int tid  = threadIdx.x;
    const int wid  = tid >> 5;
    const int lane = tid & 31;
    // heavy (high-qb) blocks first to fill the tail wave with short blocks
    const int qb = (SLQ / 64 - 1) - blockIdx.x;
    const int h = blockIdx.y, nb = blockIdx.z;
    const int q0 = qb * 64;

    const int len = g_len[nb];
    const float esc = rsqrtf((float)len) * 1.4426950408889634f;  // r*log2(e)

    const size_t headQ = (((size_t)nb * NH + h) * SLQ) * HD;
    const size_t headK = (((size_t)nb * NH + h) * SLK) * HD;

    const int lr = tid >> 3;          // 0..15 (+16 per p)
    const int lch = tid & 7;

    // --- preamble: Q into smem[0,16K), frags to regs, then area is recycled
    {
#pragma unroll
        for (int p = 0; p < 4; ++p) {
            int rr = lr + p * 16;
            uint32_t o = sw(rr, lch);
            const size_t g = headQ + (size_t)(q0 + rr) * HD + lch * 8;
            cp16(sb + o,        g_Qh + g);
            cp16(sb + 8192 + o, g_Ql + g);
        }
        CP_COMMIT();
    }
    CP_WAIT(0);
    __syncthreads();

    uint32_t qa_h[4][4], qa_l[4][4];
    {
        const int ar = wid * 16 + (lane & 15);
        const int asel = lane >> 4;
#pragma unroll
        for (int kc = 0; kc < 4; ++kc) {
            uint32_t o = sw(ar, 2 * kc + asel);
            ldm_x4(qa_h[kc], sb + o);
            ldm_x4(qa_l[kc], sb + 8192 + o);
        }
    }
    __syncthreads();   // all warps done reading Q area before KV overwrites it

    const int nkt_c = qb + 1;
    const int nkt_l = (len + 63) >> 6;
    const int nkt = (nkt_c < nkt_l) ? nkt_c : nkt_l;

    // KV stage loader: buf b in {0,1}, layout Kh|Kl|Vh|Vl @ 8KB each
    auto kvload = [&](int b, int k0) {
        const uint32_t base = sb + (uint32_t)b * 32768;
#pragma unroll
        for (int p = 0; p < 4; ++p) {
            int rr = lr + p * 16;
            uint32_t o = sw(rr, lch);
            const size_t g = headK + (size_t)(k0 + rr) * HD + lch * 8;
            cp16(base + o,         g_Kh + g);
            cp16(base + 8192 + o,  g_Kl + g);
            cp16(base + 16384 + o, g_Vh + g);
            cp16(base + 24576 + o, g_Vl + g);
        }
        CP_COMMIT();
    };
    kvload(0, 0);

    float o_[8][4];
#pragma unroll
    for (int nt = 0; nt < 8; ++nt)
#pragma unroll
        for (int q = 0; q < 4; ++q) o_[nt][q] = 0.0f;
    float m0r = -1e30f, m1r = -1e30f, l0r = 0.0f, l1r = 0.0f;

    const int row0 = q0 + wid * 16 + (lane >> 2);   // c0,c1 row
    const int kbr = (lane & 7) + ((lane >> 4) << 3);
    const int kbsel = (lane >> 3) & 1;
    const int vbr = (lane & 7) + (((lane >> 3) & 1) << 3);
    const int vbsel = lane >> 4;

    for (int kt = 0; kt < nkt; ++kt) {
        const int k0 = kt * 64;
        CP_WAIT(0);        // KV[kt] landed
        __syncthreads();   // visible to all; prior tile reads complete
        if (kt + 1 < nkt) kvload((kt + 1) & 1, k0 + 64);  // prefetch

        const uint32_t base = sb + (uint32_t)(kt & 1) * 32768;

        // S = Q K^T (full 3-term split; raw, unscaled scores)
        float s[8][4];
#pragma unroll
        for (int nt = 0; nt < 8; ++nt)
#pragma unroll
            for (int q = 0; q < 4; ++q) s[nt][q] = 0.0f;

#pragma unroll
        for (int nt2 = 0; nt2 < 4; ++nt2) {
#pragma unroll
            for (int kc = 0; kc < 4; ++kc) {
                uint32_t bo = sw(nt2 * 16 + kbr, 2 * kc + kbsel);
                uint32_t kh[4], kl[4];
                ldm_x4(kh, base + bo);
                ldm_x4(kl, base + 8192 + bo);
#pragma unroll
                for (int t = 0; t < 2; ++t) {
                    float* cc = s[2 * nt2 + t];
                    mma_bf16(cc, qa_h[kc], kh[2 * t], kh[2 * t + 1]);
                    mma_bf16(cc, qa_h[kc], kl[2 * t], kl[2 * t + 1]);
                    mma_bf16(cc, qa_l[kc], kh[2 * t], kh[2 * t + 1]);
                }
            }
        }

        // mask only boundary tiles (diagonal or length edge); raw -1e30
        if (kt == qb || k0 + 64 > len) {
#pragma unroll
            for (int nt = 0; nt < 8; ++nt) {
                int kcol = k0 + nt * 8 + 2 * (lane & 3);
#pragma unroll
                for (int q = 0; q < 4; ++q) {
                    int kk = kcol + (q & 1);
                    int qq = row0 + (q >> 1) * 8;
                    if (kk > qq || kk >= len) s[nt][q] = -1e30f;
                }
            }
        }

        // online softmax on raw scores; scale folded into exp via esc
        float mx0 = -1e30f, mx1 = -1e30f;
#pragma unroll
        for (int nt = 0; nt < 8; ++nt) {
            mx0 = fmaxf(mx0, fmaxf(s[nt][0], s[nt][1]));
            mx1 = fmaxf(mx1, fmaxf(s[nt][2], s[nt][3]));
        }
        mx0 = fmaxf(mx0, __shfl_xor_sync(0xffffffffu, mx0, 1));
        mx0 = fmaxf(mx0, __shfl_xor_sync(0xffffffffu, mx0, 2));
        mx1 = fmaxf(mx1, __shfl_xor_sync(0xffffffffu, mx1, 1));
        mx1 = fmaxf(mx1, __shfl_xor_sync(0xffffffffu, mx1, 2));
        float mn0 = fmaxf(m0r, mx0), mn1 = fmaxf(m1r, mx1);
        float a0 = fast_exp_sc(m0r - mn0, esc), a1 = fast_exp_sc(m1r - mn1, esc);
        float sum0 = 0.0f, sum1 = 0.0f;
#pragma unroll
        for (int nt = 0; nt < 8; ++nt) {
            s[nt][0] = fast_exp_sc(s[nt][0] - mn0, esc);
            s[nt][1] = fast_exp_sc(s[nt][1] - mn0, esc);
            s[nt][2] = fast_exp_sc(s[nt][2] - mn1, esc);
            s[nt][3] = fast_exp_sc(s[nt][3] - mn1, esc);
            sum0 += s[nt][0] + s[nt][1];
            sum1 += s[nt][2] + s[nt][3];
        }
        sum0 += __shfl_xor_sync(0xffffffffu, sum0, 1);
        sum0 += __shfl_xor_sync(0xffffffffu, sum0, 2);
        sum1 += __shfl_xor_sync(0xffffffffu, sum1, 1);
        sum1 += __shfl_xor_sync(0xffffffffu, sum1, 2);
        l0r = l0r * a0 + sum0;  m0r = mn0;
        l1r = l1r * a1 + sum1;  m1r = mn1;

#pragma unroll
        for (int nt = 0; nt < 8; ++nt) {
            o_[nt][0] *= a0; o_[nt][1] *= a0;
            o_[nt][2] *= a1; o_[nt][3] *= a1;
        }

        // P·V (full 3-term split)
#pragma unroll
        for (int kc = 0; kc < 4; ++kc) {
            uint32_t pa_h[4], pa_l[4];
#pragma unroll
            for (int t2 = 0; t2 < 2; ++t2) {
                const float* sv = s[2 * kc + t2];
                float h0 = __bfloat162float(__float2bfloat16_rn(sv[0]));
                float h1 = __bfloat162float(__float2bfloat16_rn(sv[1]));
                float h2 = __bfloat162float(__float2bfloat16_rn(sv[2]));
                float h3 = __bfloat162float(__float2bfloat16_rn(sv[3]));
                pa_h[2 * t2]     = pack_bf16(h0, h1);
                pa_h[2 * t2 + 1] = pack_bf16(h2, h3);
                pa_l[2 * t2]     = pack_bf16(sv[0] - h0, sv[1] - h1);
                pa_l[2 * t2 + 1] = pack_bf16(sv[2] - h2, sv[3] - h3);
            }
#pragma unroll
            for (int dn2 = 0; dn2 < 4; ++dn2) {
                uint32_t vo = sw(kc * 16 + vbr, 2 * dn2 + vbsel);
                uint32_t vh[4], vl[4];
                ldm_x4_t(vh, base + 16384 + vo);
                ldm_x4_t(vl, base + 24576 + vo);
#pragma unroll
                for (int t = 0; t < 2; ++t) {
                    float* cc = o_[2 * dn2 + t];
                    mma_bf16(cc, pa_h, vh[2 * t], vh[2 * t + 1]);
                    mma_bf16(cc, pa_h, vl[2 * t], vl[2 * t + 1]);
                    mma_bf16(cc, pa_l, vh[2 * t], vh[2 * t + 1]);
                }
            }
        }
    }

    // write O
    float inv0 = 1.0f / l0r, inv1 = 1.0f / l1r;
#pragma unroll
    for (int nt = 0; nt < 8; ++nt) {
        int d = h * HD + nt * 8 + 2 * (lane & 3);
        float2 r0 = make_float2(o_[nt][0] * inv0, o_[nt][1] * inv0);
        float2 r1 = make_float2(o_[nt][2] * inv1, o_[nt][3] * inv1);
        *(float2*)(out + ((size_t)nb * SLQ + row0) * DM + d) = r0;
        *(float2*)(out + ((size_t)nb * SLQ + row0 + 8) * DM + d) = r1;
    }
}

// ---------------------------------------------------------------------------
extern "C" void kernel_launch(void* const* d_in, const int* in_sizes, int n_in,
                              void* d_out, int out_size) {
    const float* query = (const float*)d_in[0];
    const float* key   = (const float*)d_in[1];
    const float* Wq    = (const float*)d_in[2];
    const float* Wk    = (const float*)d_in[3];
    const float* Wv    = (const float*)d_in[4];
    const unsigned int* pm = (const unsigned int*)d_in[6];
    float* out = (float*)d_out;

    cudaFuncSetAttribute(proj_mma, cudaFuncAttributeMaxDynamicSharedMemorySize,
                         2 * PSTAGE);
    cudaFuncSetAttribute(attn_mma, cudaFuncAttributeMaxDynamicSharedMemorySize,
                         65536);

    len_kernel<<<NB, 256>>>(pm);
    split_kernel<<<dim3(XELEMS / 4 / 256, 5), 256>>>(query, key, Wq, Wk, Wv);
    proj_mma<<<dim3(DM / 128, (NB * SLQ) / 128, 3), 256, 2 * PSTAGE>>>();
    attn_mma<<<dim3(SLQ / 64, NH, NB), 128, 65536>>>(out);
}